// round 12
// baseline (speedup 1.0000x reference)
#include <cuda_runtime.h>
#include <cuda_fp16.h>
#include <cstdint>
#include <math.h>

// Problem constants
#define B_    2
#define L_    2048
#define T_    (B_*L_)        // 4096 tokens
#define E_    8
#define D_    1024
#define F_    4096
#define KTOP  2
#define NPAIR (T_*KTOP)      // 8192 pairs

// GEMM tile config (R8 tile + 5-stage deep pipeline, pd=3)
#define BM 128
#define BN 128
#define BK 32
#define NSTAGE 5

// smem pitches (bytes)
#define PA_B 80                       // A row: 32 halves = 64B + 16B pad
#define PB_B 272                      // B row: 128 halves = 256B + 16B pad
#define A_STG (BM * PA_B)             // 10240
#define B_STG (BK * PB_B)             // 8704
#define STG   (A_STG + B_STG)         // 18944
#define SMEM_GEMM (1536 + NSTAGE * STG)  // 96256 (2 CTAs = 192.5KB <= 228KB)

// ---------------- scratch (device globals; device-code access ONLY) ----------------
__device__ __half g_xh[(size_t)T_ * D_];
__device__ __half g_w1h[(size_t)E_ * D_ * F_];   // row-major [e][k=D][n=F]
__device__ __half g_w2h[(size_t)E_ * F_ * D_];   // row-major [e][k=F][n=D]
__device__ __half g_hh[(size_t)NPAIR * F_];
__device__ float  g_ybuf[(size_t)NPAIR * D_];
__device__ float  g_probs[T_ * E_];
__device__ int    g_topk_e[T_ * KTOP];
__device__ float  g_topk_w[T_ * KTOP];
__device__ int    g_expert_list[E_ * T_];
__device__ int    g_expert_count[E_];            // zero-init at load; re-zeroed by combine tail
__device__ float  g_part_pf[16 * E_];
__device__ float  g_part_pp[16 * E_];

// ---------------- helpers ----------------
__device__ __forceinline__ uint32_t smem_u32(const void* p) {
    uint32_t a;
    asm("{ .reg .u64 t; cvta.to.shared.u64 t, %1; cvt.u32.u64 %0, t; }" : "=r"(a) : "l"(p));
    return a;
}

#define CP16(dst, src)  asm volatile("cp.async.cg.shared.global [%0], [%1], 16;" :: "r"(dst), "l"(src))
#define CP_COMMIT()     asm volatile("cp.async.commit_group;" ::: "memory")
#define CP_WAIT(n)      asm volatile("cp.async.wait_group %0;" :: "n"(n) : "memory")

#define LDSM_X4(r, a) \
    asm volatile("ldmatrix.sync.aligned.m8n8.x4.shared.b16 {%0,%1,%2,%3}, [%4];" \
        : "=r"((r)[0]), "=r"((r)[1]), "=r"((r)[2]), "=r"((r)[3]) : "r"(a))

#define LDSM_X4T(r, a) \
    asm volatile("ldmatrix.sync.aligned.m8n8.x4.trans.shared.b16 {%0,%1,%2,%3}, [%4];" \
        : "=r"((r)[0]), "=r"((r)[1]), "=r"((r)[2]), "=r"((r)[3]) : "r"(a))

__device__ __forceinline__ void mma_f16(float c[4], const uint32_t a[4],
                                        uint32_t b0, uint32_t b1) {
    asm volatile(
        "mma.sync.aligned.m16n8k16.row.col.f32.f16.f16.f32 "
        "{%0,%1,%2,%3}, {%4,%5,%6,%7}, {%8,%9}, {%0,%1,%2,%3};"
        : "+f"(c[0]), "+f"(c[1]), "+f"(c[2]), "+f"(c[3])
        : "r"(a[0]), "r"(a[1]), "r"(a[2]), "r"(a[3]), "r"(b0), "r"(b1));
}

__device__ __forceinline__ float gelu_exact(float v) {
    return 0.5f * v * (1.0f + erff(v * 0.70710678118654752f));
}

// ---------------- small kernels ----------------
__global__ void gate_kernel(const float* __restrict__ x,
                            const float* __restrict__ Wg,
                            const float* __restrict__ bg) {
    int gwarp = (blockIdx.x * blockDim.x + threadIdx.x) >> 5;
    int lane  = threadIdx.x & 31;
    if (gwarp >= T_) return;
    const float* xr = x + (size_t)gwarp * D_;

    float acc[E_];
#pragma unroll
    for (int e = 0; e < E_; e++) acc[e] = 0.f;
    for (int d = lane; d < D_; d += 32) {
        float xv = xr[d];
        float4 w0 = *(const float4*)(Wg + d * E_);
        float4 w1 = *(const float4*)(Wg + d * E_ + 4);
        acc[0] += xv * w0.x; acc[1] += xv * w0.y;
        acc[2] += xv * w0.z; acc[3] += xv * w0.w;
        acc[4] += xv * w1.x; acc[5] += xv * w1.y;
        acc[6] += xv * w1.z; acc[7] += xv * w1.w;
    }
#pragma unroll
    for (int e = 0; e < E_; e++)
#pragma unroll
        for (int off = 16; off > 0; off >>= 1)
            acc[e] += __shfl_xor_sync(0xFFFFFFFFu, acc[e], off);

    if (lane == 0) {
        float s[E_];
#pragma unroll
        for (int e = 0; e < E_; e++) s[e] = acc[e] + bg[e];
        int e0 = 0;
#pragma unroll
        for (int e = 1; e < E_; e++) if (s[e] > s[e0]) e0 = e;
        int e1 = -1;
#pragma unroll
        for (int e = 0; e < E_; e++) {
            if (e == e0) continue;
            if (e1 < 0 || s[e] > s[e1]) e1 = e;
        }
        float z1 = __expf(s[e1] - s[e0]);
        float w0 = 1.0f / (1.0f + z1);
        float w1 = z1 / (1.0f + z1);
        float m = s[e0], zsum = 0.f, p[E_];
#pragma unroll
        for (int e = 0; e < E_; e++) { p[e] = __expf(s[e] - m); zsum += p[e]; }
        float inv = 1.0f / zsum;
#pragma unroll
        for (int e = 0; e < E_; e++) g_probs[gwarp * E_ + e] = p[e] * inv;
        g_topk_e[gwarp * 2 + 0] = e0;
        g_topk_e[gwarp * 2 + 1] = e1;
        g_topk_w[gwarp * 2 + 0] = w0;
        g_topk_w[gwarp * 2 + 1] = w1;
    }
}

__global__ void route_kernel() {
    int t = blockIdx.x * blockDim.x + threadIdx.x;
    if (t >= T_) return;
#pragma unroll
    for (int k = 0; k < KTOP; k++) {
        int e = g_topk_e[t * 2 + k];
        int pos = atomicAdd(&g_expert_count[e], 1);
        g_expert_list[e * T_ + pos] = t * 2 + k;
    }
}

// fused converts: x -> g_xh, W1 -> g_w1h, W2 -> g_w2h (one launch)
#define NX4  (T_ * D_ / 4)
#define NW4  (E_ * D_ * F_ / 4)
__global__ void cvt_all_kernel(const float* __restrict__ x,
                               const float* __restrict__ W1,
                               const float* __restrict__ W2) {
    int i = blockIdx.x * blockDim.x + threadIdx.x;
    const float* src;
    __half* dst;
    size_t j;
    if (i < NX4)                { src = x;  dst = g_xh;  j = i; }
    else if (i < NX4 + NW4)     { src = W1; dst = g_w1h; j = i - NX4; }
    else if (i < NX4 + 2 * NW4) { src = W2; dst = g_w2h; j = i - NX4 - NW4; }
    else return;
    float4 v = *(const float4*)(src + j * 4);
    ((__half2*)dst)[2 * j]     = __floats2half2_rn(v.x, v.y);
    ((__half2*)dst)[2 * j + 1] = __floats2half2_rn(v.z, v.w);
}

__global__ void loss1_kernel() {
    __shared__ float spp[E_][257];
    __shared__ float spf[E_][257];
    int tid = threadIdx.x;
    int t = blockIdx.x * 256 + tid;
    float f[E_];
#pragma unroll
    for (int e = 0; e < E_; e++) f[e] = 0.f;
    f[g_topk_e[2 * t]]     += 1.f;
    f[g_topk_e[2 * t + 1]] += 1.f;
#pragma unroll
    for (int e = 0; e < E_; e++) {
        spp[e][tid] = g_probs[t * E_ + e];
        spf[e][tid] = f[e];
    }
    __syncthreads();
    int wid = tid >> 5, lane = tid & 31;
    if (wid < E_) {
        float a = 0.f, b = 0.f;
#pragma unroll
        for (int j = 0; j < 8; j++) {
            a += spf[wid][lane + j * 32];
            b += spp[wid][lane + j * 32];
        }
#pragma unroll
        for (int off = 16; off > 0; off >>= 1) {
            a += __shfl_xor_sync(0xFFFFFFFFu, a, off);
            b += __shfl_xor_sync(0xFFFFFFFFu, b, off);
        }
        if (lane == 0) {
            g_part_pf[blockIdx.x * E_ + wid] = a;
            g_part_pp[blockIdx.x * E_ + wid] = b;
        }
    }
}

__global__ void loss2_kernel(float* __restrict__ out) {
    __shared__ float sl[E_];
    int e = threadIdx.x;
    if (e < E_) {
        float a = 0.f, b = 0.f;
        for (int i = 0; i < 16; i++) { a += g_part_pf[i * E_ + e]; b += g_part_pp[i * E_ + e]; }
        sl[e] = (a / (float)T_) * (b / (float)T_);
    }
    __syncthreads();
    if (e == 0) {
        float loss = 0.f;
        for (int i = 0; i < E_; i++) loss += sl[i];
        out[(size_t)T_ * D_] = loss * (float)E_;
    }
}

// ---------------- 5-stage pipelined fp16 GEMM, pd=3, single barrier per chunk ----------------
// smem: [0,512) sP, [512,1024) sW, [1024,1536) sB, stages at 1536 + s*STG
template <int MODE>
__global__ void __launch_bounds__(256, 2)
ffn_gemm(const float* __restrict__ bias_g) {
    constexpr int KDIM = (MODE == 1) ? D_ : F_;
    constexpr int NDIM = (MODE == 1) ? F_ : D_;
    constexpr int CHUNKS = KDIM / BK;

    const int e     = blockIdx.y >> 5;
    const int mtile = blockIdx.y & 31;
    const int cnt   = g_expert_count[e];
    const int m0    = mtile * BM;
    if (m0 >= cnt) return;
    const int nb = blockIdx.x * BN;

    extern __shared__ char smem[];
    const uint32_t sbase = smem_u32(smem);
    int*   sP = (int*)smem;
    float* sW = (float*)(smem + 512);
    float* sB = (float*)(smem + 1024);

    const int tid = threadIdx.x;
    const int warp = tid >> 5, lane = tid & 31;

    {
        if (tid < 128) {
            int idx = m0 + tid;
            int p = (idx < cnt) ? g_expert_list[e * T_ + idx] : -1;
            sP[tid] = p;
            sW[tid] = (MODE == 2 && p >= 0) ? g_topk_w[p] : 0.f;
        } else {
            sB[tid - 128] = __ldg(bias_g + (size_t)e * NDIM + nb + (tid - 128));
        }
    }
    __syncthreads();

    const int qa = tid & 3;
    const __half* aSrc[2];
#pragma unroll
    for (int i = 0; i < 2; i++) {
        int r = (tid >> 2) + i * 64;
        int p = sP[r];
        if (p < 0) p = g_expert_list[e * T_];
        aSrc[i] = ((MODE == 1) ? (g_xh + (size_t)(p >> 1) * D_)
                               : (g_hh + (size_t)p * F_)) + qa * 8;
    }
    const __half* Wmat = ((MODE == 1) ? g_w1h : g_w2h) + (size_t)e * KDIM * NDIM;
    const int qb = tid & 15;

    uint32_t stgBase[NSTAGE];
#pragma unroll
    for (int s = 0; s < NSTAGE; s++) stgBase[s] = sbase + 1536u + s * STG;

    auto load_stage = [&](int c, int s) {
        const int k0 = c * BK;
#pragma unroll
        for (int i = 0; i < 2; i++) {
            int r = (tid >> 2) + i * 64;
            CP16(stgBase[s] + (uint32_t)(r * PA_B + qa * 16), aSrc[i] + k0);
        }
#pragma unroll
        for (int i = 0; i < 2; i++) {
            int rb = (tid >> 4) + i * 16;
            CP16(stgBase[s] + A_STG + (uint32_t)(rb * PB_B + qb * 16),
                 Wmat + (size_t)(k0 + rb) * NDIM + nb + qb * 8);
        }
        CP_COMMIT();
    };

    const int wm = warp >> 2;
    const int wn = warp & 3;
    const int gid = lane >> 2, tig = lane & 3;

    const uint32_t offA0 = (uint32_t)((wm * 64 + (lane & 15)) * PA_B + (lane >> 4) * 16);
    const uint32_t offB0 = (uint32_t)(A_STG + (((lane >> 3) & 1) * 8 + (lane & 7)) * PB_B
                                      + (wn * 32 + (lane >> 4) * 8) * 2);

    float acc[4][4][4];
#pragma unroll
    for (int mi = 0; mi < 4; mi++)
#pragma unroll
        for (int ni = 0; ni < 4; ni++)
#pragma unroll
            for (int qq = 0; qq < 4; qq++) acc[mi][ni][qq] = 0.f;

    load_stage(0, 0);
    load_stage(1, 1);
    load_stage(2, 2);

    for (int c = 0; c < CHUNKS; c++) {
        const int s = c - (c / NSTAGE) * NSTAGE;   // c % 5
        // prefetch distance 3: buffer (c+3)%5 == (c-2)%5 was last read at
        // compute(c-2), fenced by iteration c-1's barrier (which precedes
        // this load) -> safe without a second barrier.
        if (c + 3 < CHUNKS) {
            int s3 = c + 3; s3 -= (s3 / NSTAGE) * NSTAGE;
            load_stage(c + 3, s3);
            CP_WAIT(3);
        } else if (c + 2 < CHUNKS) {
            CP_WAIT(2);
        } else if (c + 1 < CHUNKS) {
            CP_WAIT(1);
        } else {
            CP_WAIT(0);
        }
        __syncthreads();   // single barrier: chunk-c data visible to all warps

        const uint32_t base = stgBase[s];
#pragma unroll
        for (int ks = 0; ks < 2; ks++) {
            uint32_t a[4][4];
            uint32_t b[2][4];
#pragma unroll
            for (int mi = 0; mi < 4; mi++)
                LDSM_X4(a[mi], base + offA0 + (uint32_t)(mi * 16 * PA_B + ks * 32));
#pragma unroll
            for (int np = 0; np < 2; np++)
                LDSM_X4T(b[np], base + offB0 + (uint32_t)(ks * 16 * PB_B + np * 32));
#pragma unroll
            for (int mi = 0; mi < 4; mi++)
#pragma unroll
                for (int ni = 0; ni < 4; ni++)
                    mma_f16(acc[mi][ni], a[mi],
                            b[ni >> 1][(ni & 1) * 2], b[ni >> 1][(ni & 1) * 2 + 1]);
        }
    }

    // epilogue
#pragma unroll
    for (int mi = 0; mi < 4; mi++) {
#pragma unroll
        for (int ni = 0; ni < 4; ni++) {
            int cl = wn * 32 + ni * 8 + tig * 2;
            int c0 = nb + cl;
            float bi0 = sB[cl];
            float bi1 = sB[cl + 1];
#pragma unroll
            for (int half = 0; half < 2; half++) {
                int r = wm * 64 + mi * 16 + gid + half * 8;
                int p = sP[r];
                if (p >= 0) {
                    float v0 = acc[mi][ni][half * 2 + 0] + bi0;
                    float v1 = acc[mi][ni][half * 2 + 1] + bi1;
                    if (MODE == 1) {
                        v0 = gelu_exact(v0);
                        v1 = gelu_exact(v1);
                        *(__half2*)(g_hh + (size_t)p * F_ + c0) = __floats2half2_rn(v0, v1);
                    } else {
                        float w = sW[r];
                        *(float2*)(g_ybuf + (size_t)p * D_ + c0) = make_float2(v0 * w, v1 * w);
                    }
                }
            }
        }
    }
}

// ---------------- combine (+ counter reset for next replay) ----------------
__global__ void combine_kernel(float* __restrict__ out) {
    int i = blockIdx.x * blockDim.x + threadIdx.x;
    if (i < E_) g_expert_count[i] = 0;   // GEMMs are done; reset for next graph replay
    if (i >= T_ * D_ / 4) return;
    int t = i / (D_ / 4);
    int dq = i % (D_ / 4);
    float4 a = *(const float4*)(g_ybuf + (size_t)(2 * t) * D_ + dq * 4);
    float4 b = *(const float4*)(g_ybuf + (size_t)(2 * t + 1) * D_ + dq * 4);
    float4 r;
    r.x = a.x + b.x; r.y = a.y + b.y; r.z = a.z + b.z; r.w = a.w + b.w;
    *(float4*)(out + (size_t)i * 4) = r;
}

// ---------------- launch ----------------
// Order keeps ffn_gemm<1> as the 4th launch (the ncu capture slot).
extern "C" void kernel_launch(void* const* d_in, const int* in_sizes, int n_in,
                              void* d_out, int out_size) {
    const float* x  = (const float*)d_in[0];
    const float* Wg = (const float*)d_in[1];
    const float* bg = (const float*)d_in[2];
    const float* W1 = (const float*)d_in[3];
    const float* b1 = (const float*)d_in[4];
    const float* W2 = (const float*)d_in[5];
    const float* b2 = (const float*)d_in[6];
    float* out = (float*)d_out;

    static bool attr_set = false;
    if (!attr_set) {
        cudaFuncSetAttribute(ffn_gemm<1>, cudaFuncAttributeMaxDynamicSharedMemorySize, SMEM_GEMM);
        cudaFuncSetAttribute(ffn_gemm<2>, cudaFuncAttributeMaxDynamicSharedMemorySize, SMEM_GEMM);
        attr_set = true;
    }

    // 1: gating
    gate_kernel<<<T_ / 8, 256>>>(x, Wg, bg);
    // 2: routing
    route_kernel<<<T_ / 256, 256>>>();
    // 3: all fp16 converts fused
    {
        int total = NX4 + 2 * NW4;
        cvt_all_kernel<<<(total + 255) / 256, 256>>>(x, W1, W2);
    }
    // 4: GEMM1  <-- ncu capture slot
    dim3 g1(F_ / BN, E_ * 32);
    ffn_gemm<1><<<g1, 256, SMEM_GEMM>>>(b1);
    // 5: GEMM2
    dim3 g2(D_ / BN, E_ * 32);
    ffn_gemm<2><<<g2, 256, SMEM_GEMM>>>(b2);
    // 6: combine + counter reset
    combine_kernel<<<(T_ * D_ / 4 + 255) / 256, 256>>>(out);
    // 7-8: load-balance loss
    loss1_kernel<<<16, 256>>>();
    loss2_kernel<<<1, 32>>>(out);
}

// round 13
// speedup vs baseline: 1.1412x; 1.1412x over previous
#include <cuda_runtime.h>
#include <cuda_fp16.h>
#include <cstdint>
#include <math.h>

// Problem constants
#define B_    2
#define L_    2048
#define T_    (B_*L_)        // 4096 tokens
#define E_    8
#define D_    1024
#define F_    4096
#define KTOP  2
#define NPAIR (T_*KTOP)      // 8192 pairs

// GEMM tile config: BK=64 chunks, 3 stages, pd=1, one barrier per chunk
#define BM 128
#define BN 128
#define BK 64
#define NSTAGE 3

// smem pitches (bytes)
#define PA_B 144                      // A row: 64 halves = 128B + 16B pad (p16=9, conflict-free)
#define PB_B 272                      // B row: 128 halves = 256B + 16B pad (p16=17, conflict-free)
#define A_STG (BM * PA_B)             // 18432
#define B_STG (BK * PB_B)             // 17408
#define STG   (A_STG + B_STG)         // 35840
#define SMEM_GEMM (1536 + NSTAGE * STG)  // 109056 (2 CTAs = 218112 <= 228KB)

// ---------------- scratch (device globals; device-code access ONLY) ----------------
__device__ __half g_xh[(size_t)T_ * D_];
__device__ __half g_w1h[(size_t)E_ * D_ * F_];   // row-major [e][k=D][n=F]
__device__ __half g_w2h[(size_t)E_ * F_ * D_];   // row-major [e][k=F][n=D]
__device__ __half g_hh[(size_t)NPAIR * F_];
__device__ float  g_ybuf[(size_t)NPAIR * D_];
__device__ float  g_probs[T_ * E_];
__device__ int    g_topk_e[T_ * KTOP];
__device__ float  g_topk_w[T_ * KTOP];
__device__ int    g_expert_list[E_ * T_];
__device__ int    g_expert_count[E_];            // zero-init at load; re-zeroed by combine tail
__device__ float  g_part_pf[16 * E_];
__device__ float  g_part_pp[16 * E_];

// ---------------- helpers ----------------
__device__ __forceinline__ uint32_t smem_u32(const void* p) {
    uint32_t a;
    asm("{ .reg .u64 t; cvta.to.shared.u64 t, %1; cvt.u32.u64 %0, t; }" : "=r"(a) : "l"(p));
    return a;
}

#define CP16(dst, src)  asm volatile("cp.async.cg.shared.global [%0], [%1], 16;" :: "r"(dst), "l"(src))
#define CP_COMMIT()     asm volatile("cp.async.commit_group;" ::: "memory")
#define CP_WAIT(n)      asm volatile("cp.async.wait_group %0;" :: "n"(n) : "memory")

#define LDSM_X4(r, a) \
    asm volatile("ldmatrix.sync.aligned.m8n8.x4.shared.b16 {%0,%1,%2,%3}, [%4];" \
        : "=r"((r)[0]), "=r"((r)[1]), "=r"((r)[2]), "=r"((r)[3]) : "r"(a))

#define LDSM_X4T(r, a) \
    asm volatile("ldmatrix.sync.aligned.m8n8.x4.trans.shared.b16 {%0,%1,%2,%3}, [%4];" \
        : "=r"((r)[0]), "=r"((r)[1]), "=r"((r)[2]), "=r"((r)[3]) : "r"(a))

__device__ __forceinline__ void mma_f16(float c[4], const uint32_t a[4],
                                        uint32_t b0, uint32_t b1) {
    asm volatile(
        "mma.sync.aligned.m16n8k16.row.col.f32.f16.f16.f32 "
        "{%0,%1,%2,%3}, {%4,%5,%6,%7}, {%8,%9}, {%0,%1,%2,%3};"
        : "+f"(c[0]), "+f"(c[1]), "+f"(c[2]), "+f"(c[3])
        : "r"(a[0]), "r"(a[1]), "r"(a[2]), "r"(a[3]), "r"(b0), "r"(b1));
}

__device__ __forceinline__ float gelu_exact(float v) {
    return 0.5f * v * (1.0f + erff(v * 0.70710678118654752f));
}

// ---------------- small kernels ----------------
__global__ void gate_kernel(const float* __restrict__ x,
                            const float* __restrict__ Wg,
                            const float* __restrict__ bg) {
    int gwarp = (blockIdx.x * blockDim.x + threadIdx.x) >> 5;
    int lane  = threadIdx.x & 31;
    if (gwarp >= T_) return;
    const float* xr = x + (size_t)gwarp * D_;

    float acc[E_];
#pragma unroll
    for (int e = 0; e < E_; e++) acc[e] = 0.f;
    for (int d = lane; d < D_; d += 32) {
        float xv = xr[d];
        float4 w0 = *(const float4*)(Wg + d * E_);
        float4 w1 = *(const float4*)(Wg + d * E_ + 4);
        acc[0] += xv * w0.x; acc[1] += xv * w0.y;
        acc[2] += xv * w0.z; acc[3] += xv * w0.w;
        acc[4] += xv * w1.x; acc[5] += xv * w1.y;
        acc[6] += xv * w1.z; acc[7] += xv * w1.w;
    }
#pragma unroll
    for (int e = 0; e < E_; e++)
#pragma unroll
        for (int off = 16; off > 0; off >>= 1)
            acc[e] += __shfl_xor_sync(0xFFFFFFFFu, acc[e], off);

    if (lane == 0) {
        float s[E_];
#pragma unroll
        for (int e = 0; e < E_; e++) s[e] = acc[e] + bg[e];
        int e0 = 0;
#pragma unroll
        for (int e = 1; e < E_; e++) if (s[e] > s[e0]) e0 = e;
        int e1 = -1;
#pragma unroll
        for (int e = 0; e < E_; e++) {
            if (e == e0) continue;
            if (e1 < 0 || s[e] > s[e1]) e1 = e;
        }
        float z1 = __expf(s[e1] - s[e0]);
        float w0 = 1.0f / (1.0f + z1);
        float w1 = z1 / (1.0f + z1);
        float m = s[e0], zsum = 0.f, p[E_];
#pragma unroll
        for (int e = 0; e < E_; e++) { p[e] = __expf(s[e] - m); zsum += p[e]; }
        float inv = 1.0f / zsum;
#pragma unroll
        for (int e = 0; e < E_; e++) g_probs[gwarp * E_ + e] = p[e] * inv;
        g_topk_e[gwarp * 2 + 0] = e0;
        g_topk_e[gwarp * 2 + 1] = e1;
        g_topk_w[gwarp * 2 + 0] = w0;
        g_topk_w[gwarp * 2 + 1] = w1;
    }
}

__global__ void route_kernel() {
    int t = blockIdx.x * blockDim.x + threadIdx.x;
    if (t >= T_) return;
#pragma unroll
    for (int k = 0; k < KTOP; k++) {
        int e = g_topk_e[t * 2 + k];
        int pos = atomicAdd(&g_expert_count[e], 1);
        g_expert_list[e * T_ + pos] = t * 2 + k;
    }
}

// fused converts: x -> g_xh, W1 -> g_w1h, W2 -> g_w2h (one launch)
#define NX4  (T_ * D_ / 4)
#define NW4  (E_ * D_ * F_ / 4)
__global__ void cvt_all_kernel(const float* __restrict__ x,
                               const float* __restrict__ W1,
                               const float* __restrict__ W2) {
    int i = blockIdx.x * blockDim.x + threadIdx.x;
    const float* src;
    __half* dst;
    size_t j;
    if (i < NX4)                { src = x;  dst = g_xh;  j = i; }
    else if (i < NX4 + NW4)     { src = W1; dst = g_w1h; j = i - NX4; }
    else if (i < NX4 + 2 * NW4) { src = W2; dst = g_w2h; j = i - NX4 - NW4; }
    else return;
    float4 v = *(const float4*)(src + j * 4);
    ((__half2*)dst)[2 * j]     = __floats2half2_rn(v.x, v.y);
    ((__half2*)dst)[2 * j + 1] = __floats2half2_rn(v.z, v.w);
}

__global__ void loss1_kernel() {
    __shared__ float spp[E_][257];
    __shared__ float spf[E_][257];
    int tid = threadIdx.x;
    int t = blockIdx.x * 256 + tid;
    float f[E_];
#pragma unroll
    for (int e = 0; e < E_; e++) f[e] = 0.f;
    f[g_topk_e[2 * t]]     += 1.f;
    f[g_topk_e[2 * t + 1]] += 1.f;
#pragma unroll
    for (int e = 0; e < E_; e++) {
        spp[e][tid] = g_probs[t * E_ + e];
        spf[e][tid] = f[e];
    }
    __syncthreads();
    int wid = tid >> 5, lane = tid & 31;
    if (wid < E_) {
        float a = 0.f, b = 0.f;
#pragma unroll
        for (int j = 0; j < 8; j++) {
            a += spf[wid][lane + j * 32];
            b += spp[wid][lane + j * 32];
        }
#pragma unroll
        for (int off = 16; off > 0; off >>= 1) {
            a += __shfl_xor_sync(0xFFFFFFFFu, a, off);
            b += __shfl_xor_sync(0xFFFFFFFFu, b, off);
        }
        if (lane == 0) {
            g_part_pf[blockIdx.x * E_ + wid] = a;
            g_part_pp[blockIdx.x * E_ + wid] = b;
        }
    }
}

__global__ void loss2_kernel(float* __restrict__ out) {
    __shared__ float sl[E_];
    int e = threadIdx.x;
    if (e < E_) {
        float a = 0.f, b = 0.f;
        for (int i = 0; i < 16; i++) { a += g_part_pf[i * E_ + e]; b += g_part_pp[i * E_ + e]; }
        sl[e] = (a / (float)T_) * (b / (float)T_);
    }
    __syncthreads();
    if (e == 0) {
        float loss = 0.f;
        for (int i = 0; i < E_; i++) loss += sl[i];
        out[(size_t)T_ * D_] = loss * (float)E_;
    }
}

// ---------------- BK=64, 3-stage, pd=1, one barrier per chunk ----------------
// smem: [0,512) sP, [512,1024) sW, [1024,1536) sB, stages at 1536 + s*STG
template <int MODE>
__global__ void __launch_bounds__(256, 2)
ffn_gemm(const float* __restrict__ bias_g) {
    constexpr int KDIM = (MODE == 1) ? D_ : F_;
    constexpr int NDIM = (MODE == 1) ? F_ : D_;
    constexpr int CHUNKS = KDIM / BK;     // 16 / 64

    const int e     = blockIdx.y >> 5;
    const int mtile = blockIdx.y & 31;
    const int cnt   = g_expert_count[e];
    const int m0    = mtile * BM;
    if (m0 >= cnt) return;
    const int nb = blockIdx.x * BN;

    extern __shared__ char smem[];
    const uint32_t sbase = smem_u32(smem);
    int*   sP = (int*)smem;
    float* sW = (float*)(smem + 512);
    float* sB = (float*)(smem + 1024);

    const int tid = threadIdx.x;
    const int warp = tid >> 5, lane = tid & 31;

    {
        if (tid < 128) {
            int idx = m0 + tid;
            int p = (idx < cnt) ? g_expert_list[e * T_ + idx] : -1;
            sP[tid] = p;
            sW[tid] = (MODE == 2 && p >= 0) ? g_topk_w[p] : 0.f;
        } else {
            sB[tid - 128] = __ldg(bias_g + (size_t)e * NDIM + nb + (tid - 128));
        }
    }
    __syncthreads();

    // A gmem sources: rows r = (tid>>3) + i*32 (i<4); 16B chunk qa = tid&7
    const int qa = tid & 7;
    const __half* aSrc[4];
#pragma unroll
    for (int i = 0; i < 4; i++) {
        int r = (tid >> 3) + i * 32;
        int p = sP[r];
        if (p < 0) p = g_expert_list[e * T_];
        aSrc[i] = ((MODE == 1) ? (g_xh + (size_t)(p >> 1) * D_)
                               : (g_hh + (size_t)p * F_)) + qa * 8;
    }
    const __half* Wmat = ((MODE == 1) ? g_w1h : g_w2h) + (size_t)e * KDIM * NDIM;
    const int qb = tid & 15;   // 16 x 16B = 256B per k-row

    uint32_t stgBase[NSTAGE];
#pragma unroll
    for (int s = 0; s < NSTAGE; s++) stgBase[s] = sbase + 1536u + s * STG;

    auto load_stage = [&](int c, int s) {
        const int k0 = c * BK;
        // A: 128 rows x 128B (1024 x 16B, 4/thread)
#pragma unroll
        for (int i = 0; i < 4; i++) {
            int r = (tid >> 3) + i * 32;
            CP16(stgBase[s] + (uint32_t)(r * PA_B + qa * 16), aSrc[i] + k0);
        }
        // B: 64 rows x 256B (1024 x 16B, 4/thread)
#pragma unroll
        for (int i = 0; i < 4; i++) {
            int rb = (tid >> 4) + i * 16;
            CP16(stgBase[s] + A_STG + (uint32_t)(rb * PB_B + qb * 16),
                 Wmat + (size_t)(k0 + rb) * NDIM + nb + qb * 8);
        }
        CP_COMMIT();
    };

    const int wm = warp >> 2;
    const int wn = warp & 3;
    const int gid = lane >> 2, tig = lane & 3;

    const uint32_t offA0 = (uint32_t)((wm * 64 + (lane & 15)) * PA_B + (lane >> 4) * 16);
    const uint32_t offB0 = (uint32_t)(A_STG + (((lane >> 3) & 1) * 8 + (lane & 7)) * PB_B
                                      + (wn * 32 + (lane >> 4) * 8) * 2);

    float acc[4][4][4];
#pragma unroll
    for (int mi = 0; mi < 4; mi++)
#pragma unroll
        for (int ni = 0; ni < 4; ni++)
#pragma unroll
            for (int qq = 0; qq < 4; qq++) acc[mi][ni][qq] = 0.f;

    load_stage(0, 0);

    int s = 0;
    for (int c = 0; c < CHUNKS; c++) {
        // pd=1: buffer (c+1)%3 was last read at compute(c-2), fenced by the
        // barrier of iteration c-1 (which precedes this load for all warps).
        if (c + 1 < CHUNKS) {
            int s1 = s + 1; if (s1 >= NSTAGE) s1 = 0;
            load_stage(c + 1, s1);
            CP_WAIT(1);
        } else {
            CP_WAIT(0);
        }
        __syncthreads();   // single barrier: chunk-c data visible to all warps

        const uint32_t base = stgBase[s];
#pragma unroll
        for (int ks = 0; ks < 4; ks++) {
            uint32_t a[4][4];
            uint32_t b[2][4];
#pragma unroll
            for (int mi = 0; mi < 4; mi++)
                LDSM_X4(a[mi], base + offA0 + (uint32_t)(mi * 16 * PA_B + ks * 32));
#pragma unroll
            for (int np = 0; np < 2; np++)
                LDSM_X4T(b[np], base + offB0 + (uint32_t)(ks * 16 * PB_B + np * 32));
#pragma unroll
            for (int mi = 0; mi < 4; mi++)
#pragma unroll
                for (int ni = 0; ni < 4; ni++)
                    mma_f16(acc[mi][ni], a[mi],
                            b[ni >> 1][(ni & 1) * 2], b[ni >> 1][(ni & 1) * 2 + 1]);
        }
        s++; if (s >= NSTAGE) s = 0;
    }

    // epilogue
#pragma unroll
    for (int mi = 0; mi < 4; mi++) {
#pragma unroll
        for (int ni = 0; ni < 4; ni++) {
            int cl = wn * 32 + ni * 8 + tig * 2;
            int c0 = nb + cl;
            float bi0 = sB[cl];
            float bi1 = sB[cl + 1];
#pragma unroll
            for (int half = 0; half < 2; half++) {
                int r = wm * 64 + mi * 16 + gid + half * 8;
                int p = sP[r];
                if (p >= 0) {
                    float v0 = acc[mi][ni][half * 2 + 0] + bi0;
                    float v1 = acc[mi][ni][half * 2 + 1] + bi1;
                    if (MODE == 1) {
                        v0 = gelu_exact(v0);
                        v1 = gelu_exact(v1);
                        *(__half2*)(g_hh + (size_t)p * F_ + c0) = __floats2half2_rn(v0, v1);
                    } else {
                        float w = sW[r];
                        *(float2*)(g_ybuf + (size_t)p * D_ + c0) = make_float2(v0 * w, v1 * w);
                    }
                }
            }
        }
    }
}

// ---------------- combine (+ counter reset for next replay) ----------------
__global__ void combine_kernel(float* __restrict__ out) {
    int i = blockIdx.x * blockDim.x + threadIdx.x;
    if (i < E_) g_expert_count[i] = 0;   // GEMMs are done; reset for next graph replay
    if (i >= T_ * D_ / 4) return;
    int t = i / (D_ / 4);
    int dq = i % (D_ / 4);
    float4 a = *(const float4*)(g_ybuf + (size_t)(2 * t) * D_ + dq * 4);
    float4 b = *(const float4*)(g_ybuf + (size_t)(2 * t + 1) * D_ + dq * 4);
    float4 r;
    r.x = a.x + b.x; r.y = a.y + b.y; r.z = a.z + b.z; r.w = a.w + b.w;
    *(float4*)(out + (size_t)i * 4) = r;
}

// ---------------- launch ----------------
// Order keeps ffn_gemm<1> as the 4th launch (the ncu capture slot).
extern "C" void kernel_launch(void* const* d_in, const int* in_sizes, int n_in,
                              void* d_out, int out_size) {
    const float* x  = (const float*)d_in[0];
    const float* Wg = (const float*)d_in[1];
    const float* bg = (const float*)d_in[2];
    const float* W1 = (const float*)d_in[3];
    const float* b1 = (const float*)d_in[4];
    const float* W2 = (const float*)d_in[5];
    const float* b2 = (const float*)d_in[6];
    float* out = (float*)d_out;

    static bool attr_set = false;
    if (!attr_set) {
        cudaFuncSetAttribute(ffn_gemm<1>, cudaFuncAttributeMaxDynamicSharedMemorySize, SMEM_GEMM);
        cudaFuncSetAttribute(ffn_gemm<2>, cudaFuncAttributeMaxDynamicSharedMemorySize, SMEM_GEMM);
        attr_set = true;
    }

    // 1: gating
    gate_kernel<<<T_ / 8, 256>>>(x, Wg, bg);
    // 2: routing
    route_kernel<<<T_ / 256, 256>>>();
    // 3: all fp16 converts fused
    {
        int total = NX4 + 2 * NW4;
        cvt_all_kernel<<<(total + 255) / 256, 256>>>(x, W1, W2);
    }
    // 4: GEMM1  <-- ncu capture slot
    dim3 g1(F_ / BN, E_ * 32);
    ffn_gemm<1><<<g1, 256, SMEM_GEMM>>>(b1);
    // 5: GEMM2
    dim3 g2(D_ / BN, E_ * 32);
    ffn_gemm<2><<<g2, 256, SMEM_GEMM>>>(b2);
    // 6: combine + counter reset
    combine_kernel<<<(T_ * D_ / 4 + 255) / 256, 256>>>(out);
    // 7-8: load-balance loss
    loss1_kernel<<<16, 256>>>();
    loss2_kernel<<<1, 32>>>(out);
}

// round 14
// speedup vs baseline: 1.1489x; 1.0068x over previous
#include <cuda_runtime.h>
#include <cuda_fp16.h>
#include <cstdint>
#include <math.h>

// Problem constants
#define B_    2
#define L_    2048
#define T_    (B_*L_)        // 4096 tokens
#define E_    8
#define D_    1024
#define F_    4096
#define KTOP  2
#define NPAIR (T_*KTOP)      // 8192 pairs

// GEMM tile config: BK=64 chunks, 3 stages, pd=1, one barrier per chunk (R13)
#define BM 128
#define BN 128
#define BK 64
#define NSTAGE 3

// smem pitches (bytes)
#define PA_B 144                      // A row: 64 halves = 128B + 16B pad (p16=9, conflict-free)
#define PB_B 272                      // B row: 128 halves = 256B + 16B pad (p16=17, conflict-free)
#define A_STG (BM * PA_B)             // 18432
#define B_STG (BK * PB_B)             // 17408
#define STG   (A_STG + B_STG)         // 35840
#define SMEM_GEMM (1536 + NSTAGE * STG)  // 109056 (2 CTAs = 218112 <= 228KB)

// ---------------- scratch (device globals; device-code access ONLY) ----------------
__device__ __half g_xh[(size_t)T_ * D_];
__device__ __half g_w1h[(size_t)E_ * D_ * F_];   // row-major [e][k=D][n=F]
__device__ __half g_w2h[(size_t)E_ * F_ * D_];   // row-major [e][k=F][n=D]
__device__ __half g_hh[(size_t)NPAIR * F_];
__device__ float  g_ybuf[(size_t)NPAIR * D_];
__device__ float  g_probs[T_ * E_];
__device__ int    g_topk_e[T_ * KTOP];
__device__ float  g_topk_w[T_ * KTOP];
__device__ int    g_expert_list[E_ * T_];
__device__ int    g_expert_count[E_];            // zero-init at load; re-zeroed by combine tail
__device__ float  g_part_pf[16 * E_];
__device__ float  g_part_pp[16 * E_];

// ---------------- helpers ----------------
__device__ __forceinline__ uint32_t smem_u32(const void* p) {
    uint32_t a;
    asm("{ .reg .u64 t; cvta.to.shared.u64 t, %1; cvt.u32.u64 %0, t; }" : "=r"(a) : "l"(p));
    return a;
}

#define CP16(dst, src)  asm volatile("cp.async.cg.shared.global [%0], [%1], 16;" :: "r"(dst), "l"(src))
#define CP_COMMIT()     asm volatile("cp.async.commit_group;" ::: "memory")
#define CP_WAIT(n)      asm volatile("cp.async.wait_group %0;" :: "n"(n) : "memory")

#define LDSM_X4(r, a) \
    asm volatile("ldmatrix.sync.aligned.m8n8.x4.shared.b16 {%0,%1,%2,%3}, [%4];" \
        : "=r"((r)[0]), "=r"((r)[1]), "=r"((r)[2]), "=r"((r)[3]) : "r"(a))

#define LDSM_X4T(r, a) \
    asm volatile("ldmatrix.sync.aligned.m8n8.x4.trans.shared.b16 {%0,%1,%2,%3}, [%4];" \
        : "=r"((r)[0]), "=r"((r)[1]), "=r"((r)[2]), "=r"((r)[3]) : "r"(a))

__device__ __forceinline__ void mma_f16(float c[4], const uint32_t a[4],
                                        uint32_t b0, uint32_t b1) {
    asm volatile(
        "mma.sync.aligned.m16n8k16.row.col.f32.f16.f16.f32 "
        "{%0,%1,%2,%3}, {%4,%5,%6,%7}, {%8,%9}, {%0,%1,%2,%3};"
        : "+f"(c[0]), "+f"(c[1]), "+f"(c[2]), "+f"(c[3])
        : "r"(a[0]), "r"(a[1]), "r"(a[2]), "r"(a[3]), "r"(b0), "r"(b1));
}

__device__ __forceinline__ float gelu_exact(float v) {
    return 0.5f * v * (1.0f + erff(v * 0.70710678118654752f));
}

// ---------------- gate + route + x->fp16 fused (one warp per token) ----------------
__global__ void gate_kernel(const float* __restrict__ x,
                            const float* __restrict__ Wg,
                            const float* __restrict__ bg) {
    int gwarp = (blockIdx.x * blockDim.x + threadIdx.x) >> 5;
    int lane  = threadIdx.x & 31;
    if (gwarp >= T_) return;
    const float* xr = x + (size_t)gwarp * D_;
    __half* xh = g_xh + (size_t)gwarp * D_;

    float acc[E_];
#pragma unroll
    for (int e = 0; e < E_; e++) acc[e] = 0.f;
    for (int d = lane; d < D_; d += 32) {
        float xv = xr[d];
        xh[d] = __float2half_rn(xv);            // fused x conversion
        float4 w0 = *(const float4*)(Wg + d * E_);
        float4 w1 = *(const float4*)(Wg + d * E_ + 4);
        acc[0] += xv * w0.x; acc[1] += xv * w0.y;
        acc[2] += xv * w0.z; acc[3] += xv * w0.w;
        acc[4] += xv * w1.x; acc[5] += xv * w1.y;
        acc[6] += xv * w1.z; acc[7] += xv * w1.w;
    }
#pragma unroll
    for (int e = 0; e < E_; e++)
#pragma unroll
        for (int off = 16; off > 0; off >>= 1)
            acc[e] += __shfl_xor_sync(0xFFFFFFFFu, acc[e], off);

    if (lane == 0) {
        float s[E_];
#pragma unroll
        for (int e = 0; e < E_; e++) s[e] = acc[e] + bg[e];
        int e0 = 0;
#pragma unroll
        for (int e = 1; e < E_; e++) if (s[e] > s[e0]) e0 = e;
        int e1 = -1;
#pragma unroll
        for (int e = 0; e < E_; e++) {
            if (e == e0) continue;
            if (e1 < 0 || s[e] > s[e1]) e1 = e;
        }
        float z1 = __expf(s[e1] - s[e0]);
        float w0 = 1.0f / (1.0f + z1);
        float w1 = z1 / (1.0f + z1);
        float m = s[e0], zsum = 0.f, p[E_];
#pragma unroll
        for (int e = 0; e < E_; e++) { p[e] = __expf(s[e] - m); zsum += p[e]; }
        float inv = 1.0f / zsum;
#pragma unroll
        for (int e = 0; e < E_; e++) g_probs[gwarp * E_ + e] = p[e] * inv;
        g_topk_e[gwarp * 2 + 0] = e0;
        g_topk_e[gwarp * 2 + 1] = e1;
        g_topk_w[gwarp * 2 + 0] = w0;
        g_topk_w[gwarp * 2 + 1] = w1;
        // fused routing (list order nondeterministic; pair arithmetic order-independent)
        int pos0 = atomicAdd(&g_expert_count[e0], 1);
        g_expert_list[e0 * T_ + pos0] = gwarp * 2 + 0;
        int pos1 = atomicAdd(&g_expert_count[e1], 1);
        g_expert_list[e1 * T_ + pos1] = gwarp * 2 + 1;
    }
}

// fused weight converts: W1 -> g_w1h, W2 -> g_w2h (one launch)
#define NW4  (E_ * D_ * F_ / 4)
__global__ void cvt_w_kernel(const float* __restrict__ W1,
                             const float* __restrict__ W2) {
    int i = blockIdx.x * blockDim.x + threadIdx.x;
    const float* src;
    __half* dst;
    size_t j;
    if (i < NW4)            { src = W1; dst = g_w1h; j = i; }
    else if (i < 2 * NW4)   { src = W2; dst = g_w2h; j = i - NW4; }
    else return;
    float4 v = *(const float4*)(src + j * 4);
    ((__half2*)dst)[2 * j]     = __floats2half2_rn(v.x, v.y);
    ((__half2*)dst)[2 * j + 1] = __floats2half2_rn(v.z, v.w);
}

__global__ void loss1_kernel() {
    __shared__ float spp[E_][257];
    __shared__ float spf[E_][257];
    int tid = threadIdx.x;
    int t = blockIdx.x * 256 + tid;
    float f[E_];
#pragma unroll
    for (int e = 0; e < E_; e++) f[e] = 0.f;
    f[g_topk_e[2 * t]]     += 1.f;
    f[g_topk_e[2 * t + 1]] += 1.f;
#pragma unroll
    for (int e = 0; e < E_; e++) {
        spp[e][tid] = g_probs[t * E_ + e];
        spf[e][tid] = f[e];
    }
    __syncthreads();
    int wid = tid >> 5, lane = tid & 31;
    if (wid < E_) {
        float a = 0.f, b = 0.f;
#pragma unroll
        for (int j = 0; j < 8; j++) {
            a += spf[wid][lane + j * 32];
            b += spp[wid][lane + j * 32];
        }
#pragma unroll
        for (int off = 16; off > 0; off >>= 1) {
            a += __shfl_xor_sync(0xFFFFFFFFu, a, off);
            b += __shfl_xor_sync(0xFFFFFFFFu, b, off);
        }
        if (lane == 0) {
            g_part_pf[blockIdx.x * E_ + wid] = a;
            g_part_pp[blockIdx.x * E_ + wid] = b;
        }
    }
}

__global__ void loss2_kernel(float* __restrict__ out) {
    __shared__ float sl[E_];
    int e = threadIdx.x;
    if (e < E_) {
        float a = 0.f, b = 0.f;
        for (int i = 0; i < 16; i++) { a += g_part_pf[i * E_ + e]; b += g_part_pp[i * E_ + e]; }
        sl[e] = (a / (float)T_) * (b / (float)T_);
    }
    __syncthreads();
    if (e == 0) {
        float loss = 0.f;
        for (int i = 0; i < E_; i++) loss += sl[i];
        out[(size_t)T_ * D_] = loss * (float)E_;
    }
}

// ---------------- BK=64, 3-stage, pd=1, one barrier per chunk ----------------
// smem: [0,512) sP, [512,1024) sW, [1024,1536) sB, stages at 1536 + s*STG
template <int MODE>
__global__ void __launch_bounds__(256, 2)
ffn_gemm(const float* __restrict__ bias_g) {
    constexpr int KDIM = (MODE == 1) ? D_ : F_;
    constexpr int NDIM = (MODE == 1) ? F_ : D_;
    constexpr int CHUNKS = KDIM / BK;     // 16 / 64

    const int e     = blockIdx.y >> 5;
    const int mtile = blockIdx.y & 31;
    const int cnt   = g_expert_count[e];
    const int m0    = mtile * BM;
    if (m0 >= cnt) return;
    const int nb = blockIdx.x * BN;

    extern __shared__ char smem[];
    const uint32_t sbase = smem_u32(smem);
    int*   sP = (int*)smem;
    float* sW = (float*)(smem + 512);
    float* sB = (float*)(smem + 1024);

    const int tid = threadIdx.x;
    const int warp = tid >> 5, lane = tid & 31;

    {
        if (tid < 128) {
            int idx = m0 + tid;
            int p = (idx < cnt) ? g_expert_list[e * T_ + idx] : -1;
            sP[tid] = p;
            sW[tid] = (MODE == 2 && p >= 0) ? g_topk_w[p] : 0.f;
        } else {
            sB[tid - 128] = __ldg(bias_g + (size_t)e * NDIM + nb + (tid - 128));
        }
    }
    __syncthreads();

    // A gmem sources (running pointers, advanced by BK halves per issued chunk)
    const int qa = tid & 7;
    const __half* aPtr[4];
#pragma unroll
    for (int i = 0; i < 4; i++) {
        int r = (tid >> 3) + i * 32;
        int p = sP[r];
        if (p < 0) p = g_expert_list[e * T_];
        aPtr[i] = ((MODE == 1) ? (g_xh + (size_t)(p >> 1) * D_)
                               : (g_hh + (size_t)p * F_)) + qa * 8;
    }
    const int qb = tid & 15;
    const __half* bPtr = ((MODE == 1) ? g_w1h : g_w2h) + (size_t)e * KDIM * NDIM
                         + (size_t)(tid >> 4) * NDIM + nb + qb * 8;

    // precomputed per-thread smem write offsets (stage-relative)
    uint32_t aDst[4], bDst[4];
#pragma unroll
    for (int i = 0; i < 4; i++) {
        aDst[i] = (uint32_t)(((tid >> 3) + i * 32) * PA_B + qa * 16);
        bDst[i] = (uint32_t)(A_STG + ((tid >> 4) + i * 16) * PB_B + qb * 16);
    }

    uint32_t stgBase[NSTAGE];
#pragma unroll
    for (int s = 0; s < NSTAGE; s++) stgBase[s] = sbase + 1536u + s * STG;

    auto load_stage = [&](int s) {
        const uint32_t base = stgBase[s];
#pragma unroll
        for (int i = 0; i < 4; i++)
            CP16(base + aDst[i], aPtr[i]);
#pragma unroll
        for (int i = 0; i < 4; i++)
            CP16(base + bDst[i], bPtr + (size_t)(i * 16) * NDIM);
        CP_COMMIT();
        // advance running pointers
#pragma unroll
        for (int i = 0; i < 4; i++) aPtr[i] += BK;
        bPtr += BK * (size_t)NDIM;
    };

    const int wm = warp >> 2;
    const int wn = warp & 3;
    const int gid = lane >> 2, tig = lane & 3;

    const uint32_t offA0 = (uint32_t)((wm * 64 + (lane & 15)) * PA_B + (lane >> 4) * 16);
    const uint32_t offB0 = (uint32_t)(A_STG + (((lane >> 3) & 1) * 8 + (lane & 7)) * PB_B
                                      + (wn * 32 + (lane >> 4) * 8) * 2);

    float acc[4][4][4];
#pragma unroll
    for (int mi = 0; mi < 4; mi++)
#pragma unroll
        for (int ni = 0; ni < 4; ni++)
#pragma unroll
            for (int qq = 0; qq < 4; qq++) acc[mi][ni][qq] = 0.f;

    load_stage(0);

    int s = 0;
    for (int c = 0; c < CHUNKS; c++) {
        // pd=1: buffer (c+1)%3 was last read at compute(c-2), fenced by the
        // barrier of iteration c-1 (which precedes this load for all warps).
        if (c + 1 < CHUNKS) {
            int s1 = s + 1; if (s1 >= NSTAGE) s1 = 0;
            load_stage(s1);
            CP_WAIT(1);
        } else {
            CP_WAIT(0);
        }
        __syncthreads();   // single barrier: chunk-c data visible to all warps

        const uint32_t base = stgBase[s];
#pragma unroll
        for (int ks = 0; ks < 4; ks++) {
            uint32_t a[4][4];
            uint32_t b[2][4];
#pragma unroll
            for (int mi = 0; mi < 4; mi++)
                LDSM_X4(a[mi], base + offA0 + (uint32_t)(mi * 16 * PA_B + ks * 32));
#pragma unroll
            for (int np = 0; np < 2; np++)
                LDSM_X4T(b[np], base + offB0 + (uint32_t)(ks * 16 * PB_B + np * 32));
#pragma unroll
            for (int mi = 0; mi < 4; mi++)
#pragma unroll
                for (int ni = 0; ni < 4; ni++)
                    mma_f16(acc[mi][ni], a[mi],
                            b[ni >> 1][(ni & 1) * 2], b[ni >> 1][(ni & 1) * 2 + 1]);
        }
        s++; if (s >= NSTAGE) s = 0;
    }

    // epilogue
#pragma unroll
    for (int mi = 0; mi < 4; mi++) {
#pragma unroll
        for (int ni = 0; ni < 4; ni++) {
            int cl = wn * 32 + ni * 8 + tig * 2;
            int c0 = nb + cl;
            float bi0 = sB[cl];
            float bi1 = sB[cl + 1];
#pragma unroll
            for (int half = 0; half < 2; half++) {
                int r = wm * 64 + mi * 16 + gid + half * 8;
                int p = sP[r];
                if (p >= 0) {
                    float v0 = acc[mi][ni][half * 2 + 0] + bi0;
                    float v1 = acc[mi][ni][half * 2 + 1] + bi1;
                    if (MODE == 1) {
                        v0 = gelu_exact(v0);
                        v1 = gelu_exact(v1);
                        *(__half2*)(g_hh + (size_t)p * F_ + c0) = __floats2half2_rn(v0, v1);
                    } else {
                        float w = sW[r];
                        *(float2*)(g_ybuf + (size_t)p * D_ + c0) = make_float2(v0 * w, v1 * w);
                    }
                }
            }
        }
    }
}

// ---------------- combine (+ counter reset for next replay) ----------------
__global__ void combine_kernel(float* __restrict__ out) {
    int i = blockIdx.x * blockDim.x + threadIdx.x;
    if (i < E_) g_expert_count[i] = 0;   // GEMMs are done; reset for next graph replay
    if (i >= T_ * D_ / 4) return;
    int t = i / (D_ / 4);
    int dq = i % (D_ / 4);
    float4 a = *(const float4*)(g_ybuf + (size_t)(2 * t) * D_ + dq * 4);
    float4 b = *(const float4*)(g_ybuf + (size_t)(2 * t + 1) * D_ + dq * 4);
    float4 r;
    r.x = a.x + b.x; r.y = a.y + b.y; r.z = a.z + b.z; r.w = a.w + b.w;
    *(float4*)(out + (size_t)i * 4) = r;
}

// ---------------- launch ----------------
// Order keeps ffn_gemm<1> as the 4th launch (the ncu capture slot).
extern "C" void kernel_launch(void* const* d_in, const int* in_sizes, int n_in,
                              void* d_out, int out_size) {
    const float* x  = (const float*)d_in[0];
    const float* Wg = (const float*)d_in[1];
    const float* bg = (const float*)d_in[2];
    const float* W1 = (const float*)d_in[3];
    const float* b1 = (const float*)d_in[4];
    const float* W2 = (const float*)d_in[5];
    const float* b2 = (const float*)d_in[6];
    float* out = (float*)d_out;

    static bool attr_set = false;
    if (!attr_set) {
        cudaFuncSetAttribute(ffn_gemm<1>, cudaFuncAttributeMaxDynamicSharedMemorySize, SMEM_GEMM);
        cudaFuncSetAttribute(ffn_gemm<2>, cudaFuncAttributeMaxDynamicSharedMemorySize, SMEM_GEMM);
        attr_set = true;
    }

    // 1: gating + routing + x conversion (fused)
    gate_kernel<<<T_ / 8, 256>>>(x, Wg, bg);
    // 2: weight converts (fused W1+W2)
    cvt_w_kernel<<<(2 * NW4 + 255) / 256, 256>>>(W1, W2);
    // 3: loss partials (depends only on gate outputs)
    loss1_kernel<<<16, 256>>>();
    // 4: GEMM1  <-- ncu capture slot
    dim3 g1(F_ / BN, E_ * 32);
    ffn_gemm<1><<<g1, 256, SMEM_GEMM>>>(b1);
    // 5: GEMM2
    dim3 g2(D_ / BN, E_ * 32);
    ffn_gemm<2><<<g2, 256, SMEM_GEMM>>>(b2);
    // 6: combine + counter reset
    combine_kernel<<<(T_ * D_ / 4 + 255) / 256, 256>>>(out);
    // 7: loss final
    loss2_kernel<<<1, 32>>>(out);
}

// round 15
// speedup vs baseline: 1.1592x; 1.0089x over previous
#include <cuda_runtime.h>
#include <cuda_fp16.h>
#include <cstdint>
#include <math.h>

// Problem constants
#define B_    2
#define L_    2048
#define T_    (B_*L_)        // 4096 tokens
#define E_    8
#define D_    1024
#define F_    4096
#define KTOP  2
#define NPAIR (T_*KTOP)      // 8192 pairs

// GEMM tile config: BK=64 chunks, 3 stages, pd=1, one barrier per chunk (R13/R14)
#define BM 128
#define BN 128
#define BK 64
#define NSTAGE 3

// smem pitches (bytes)
#define PA_B 144                      // A row: 64 halves = 128B + 16B pad (p16=9, conflict-free)
#define PB_B 272                      // B row: 128 halves = 256B + 16B pad (p16=17, conflict-free)
#define A_STG (BM * PA_B)             // 18432
#define B_STG (BK * PB_B)             // 17408
#define STG   (A_STG + B_STG)         // 35840
#define SMEM_GEMM (1536 + NSTAGE * STG)  // 109056 (2 CTAs = 218112 <= 228KB)

// ---------------- scratch (device globals; device-code access ONLY) ----------------
__device__ __half g_xh[(size_t)T_ * D_];
__device__ __half g_w1h[(size_t)E_ * D_ * F_];   // row-major [e][k=D][n=F]
__device__ __half g_w2h[(size_t)E_ * F_ * D_];   // row-major [e][k=F][n=D]
__device__ __half g_hh[(size_t)NPAIR * F_];
__device__ float  g_ybuf[(size_t)NPAIR * D_];
__device__ float  g_probs[T_ * E_];
__device__ int    g_topk_e[T_ * KTOP];
__device__ float  g_topk_w[T_ * KTOP];
__device__ int    g_expert_list[E_ * T_];
__device__ int    g_expert_count[E_];            // zero-init at load; re-zeroed by combine tail
__device__ float  g_part_pf[16 * E_];
__device__ float  g_part_pp[16 * E_];

// ---------------- helpers ----------------
__device__ __forceinline__ uint32_t smem_u32(const void* p) {
    uint32_t a;
    asm("{ .reg .u64 t; cvta.to.shared.u64 t, %1; cvt.u32.u64 %0, t; }" : "=r"(a) : "l"(p));
    return a;
}

#define CP16(dst, src)  asm volatile("cp.async.cg.shared.global [%0], [%1], 16;" :: "r"(dst), "l"(src))
#define CP_COMMIT()     asm volatile("cp.async.commit_group;" ::: "memory")
#define CP_WAIT(n)      asm volatile("cp.async.wait_group %0;" :: "n"(n) : "memory")

#define LDSM_X4(r, a) \
    asm volatile("ldmatrix.sync.aligned.m8n8.x4.shared.b16 {%0,%1,%2,%3}, [%4];" \
        : "=r"((r)[0]), "=r"((r)[1]), "=r"((r)[2]), "=r"((r)[3]) : "r"(a))

#define LDSM_X4T(r, a) \
    asm volatile("ldmatrix.sync.aligned.m8n8.x4.trans.shared.b16 {%0,%1,%2,%3}, [%4];" \
        : "=r"((r)[0]), "=r"((r)[1]), "=r"((r)[2]), "=r"((r)[3]) : "r"(a))

__device__ __forceinline__ void mma_f16(float c[4], const uint32_t a[4],
                                        uint32_t b0, uint32_t b1) {
    asm volatile(
        "mma.sync.aligned.m16n8k16.row.col.f32.f16.f16.f32 "
        "{%0,%1,%2,%3}, {%4,%5,%6,%7}, {%8,%9}, {%0,%1,%2,%3};"
        : "+f"(c[0]), "+f"(c[1]), "+f"(c[2]), "+f"(c[3])
        : "r"(a[0]), "r"(a[1]), "r"(a[2]), "r"(a[3]), "r"(b0), "r"(b1));
}

__device__ __forceinline__ float gelu_exact(float v) {
    return 0.5f * v * (1.0f + erff(v * 0.70710678118654752f));
}

// ---------------- prep: gate+route+x->fp16 (blocks 0..511) + weight cvt (rest) ----------------
#define GATE_BLOCKS (T_ / 8)            // 512 blocks x 8 warps = 4096 tokens
#define NW4  (E_ * D_ * F_ / 4)         // float4 units per weight tensor
#define CVT_BLOCKS ((2 * NW4 + 255) / 256)

__global__ void prep_kernel(const float* __restrict__ x,
                            const float* __restrict__ Wg,
                            const float* __restrict__ bg,
                            const float* __restrict__ W1,
                            const float* __restrict__ W2) {
    if (blockIdx.x >= GATE_BLOCKS) {
        // ---- weight conversion path ----
        int i = (blockIdx.x - GATE_BLOCKS) * blockDim.x + threadIdx.x;
        const float* src;
        __half* dst;
        size_t j;
        if (i < NW4)          { src = W1; dst = g_w1h; j = i; }
        else if (i < 2 * NW4) { src = W2; dst = g_w2h; j = i - NW4; }
        else return;
        float4 v = *(const float4*)(src + j * 4);
        ((__half2*)dst)[2 * j]     = __floats2half2_rn(v.x, v.y);
        ((__half2*)dst)[2 * j + 1] = __floats2half2_rn(v.z, v.w);
        return;
    }

    // ---- gate + route + x conversion path ----
    int gwarp = (blockIdx.x * blockDim.x + threadIdx.x) >> 5;
    int lane  = threadIdx.x & 31;
    const float* xr = x + (size_t)gwarp * D_;
    __half* xh = g_xh + (size_t)gwarp * D_;

    float acc[E_];
#pragma unroll
    for (int e = 0; e < E_; e++) acc[e] = 0.f;
    for (int d = lane; d < D_; d += 32) {
        float xv = xr[d];
        xh[d] = __float2half_rn(xv);            // fused x conversion
        float4 w0 = *(const float4*)(Wg + d * E_);
        float4 w1 = *(const float4*)(Wg + d * E_ + 4);
        acc[0] += xv * w0.x; acc[1] += xv * w0.y;
        acc[2] += xv * w0.z; acc[3] += xv * w0.w;
        acc[4] += xv * w1.x; acc[5] += xv * w1.y;
        acc[6] += xv * w1.z; acc[7] += xv * w1.w;
    }
#pragma unroll
    for (int e = 0; e < E_; e++)
#pragma unroll
        for (int off = 16; off > 0; off >>= 1)
            acc[e] += __shfl_xor_sync(0xFFFFFFFFu, acc[e], off);

    if (lane == 0) {
        float s[E_];
#pragma unroll
        for (int e = 0; e < E_; e++) s[e] = acc[e] + bg[e];
        int e0 = 0;
#pragma unroll
        for (int e = 1; e < E_; e++) if (s[e] > s[e0]) e0 = e;
        int e1 = -1;
#pragma unroll
        for (int e = 0; e < E_; e++) {
            if (e == e0) continue;
            if (e1 < 0 || s[e] > s[e1]) e1 = e;
        }
        float z1 = __expf(s[e1] - s[e0]);
        float w0 = 1.0f / (1.0f + z1);
        float w1 = z1 / (1.0f + z1);
        float m = s[e0], zsum = 0.f, p[E_];
#pragma unroll
        for (int e = 0; e < E_; e++) { p[e] = __expf(s[e] - m); zsum += p[e]; }
        float inv = 1.0f / zsum;
#pragma unroll
        for (int e = 0; e < E_; e++) g_probs[gwarp * E_ + e] = p[e] * inv;
        g_topk_e[gwarp * 2 + 0] = e0;
        g_topk_e[gwarp * 2 + 1] = e1;
        g_topk_w[gwarp * 2 + 0] = w0;
        g_topk_w[gwarp * 2 + 1] = w1;
        // fused routing (list order nondeterministic; pair arithmetic order-independent)
        int pos0 = atomicAdd(&g_expert_count[e0], 1);
        g_expert_list[e0 * T_ + pos0] = gwarp * 2 + 0;
        int pos1 = atomicAdd(&g_expert_count[e1], 1);
        g_expert_list[e1 * T_ + pos1] = gwarp * 2 + 1;
    }
}

__global__ void loss1_kernel() {
    __shared__ float spp[E_][257];
    __shared__ float spf[E_][257];
    int tid = threadIdx.x;
    int t = blockIdx.x * 256 + tid;
    float f[E_];
#pragma unroll
    for (int e = 0; e < E_; e++) f[e] = 0.f;
    f[g_topk_e[2 * t]]     += 1.f;
    f[g_topk_e[2 * t + 1]] += 1.f;
#pragma unroll
    for (int e = 0; e < E_; e++) {
        spp[e][tid] = g_probs[t * E_ + e];
        spf[e][tid] = f[e];
    }
    __syncthreads();
    int wid = tid >> 5, lane = tid & 31;
    if (wid < E_) {
        float a = 0.f, b = 0.f;
#pragma unroll
        for (int j = 0; j < 8; j++) {
            a += spf[wid][lane + j * 32];
            b += spp[wid][lane + j * 32];
        }
#pragma unroll
        for (int off = 16; off > 0; off >>= 1) {
            a += __shfl_xor_sync(0xFFFFFFFFu, a, off);
            b += __shfl_xor_sync(0xFFFFFFFFu, b, off);
        }
        if (lane == 0) {
            g_part_pf[blockIdx.x * E_ + wid] = a;
            g_part_pp[blockIdx.x * E_ + wid] = b;
        }
    }
}

__global__ void loss2_kernel(float* __restrict__ out) {
    __shared__ float sl[E_];
    int e = threadIdx.x;
    if (e < E_) {
        float a = 0.f, b = 0.f;
        for (int i = 0; i < 16; i++) { a += g_part_pf[i * E_ + e]; b += g_part_pp[i * E_ + e]; }
        sl[e] = (a / (float)T_) * (b / (float)T_);
    }
    __syncthreads();
    if (e == 0) {
        float loss = 0.f;
        for (int i = 0; i < E_; i++) loss += sl[i];
        out[(size_t)T_ * D_] = loss * (float)E_;
    }
}

// ---------------- BK=64, 3-stage, pd=1, one barrier per chunk ----------------
// smem: [0,512) sP, [512,1024) sW, [1024,1536) sB, stages at 1536 + s*STG
template <int MODE>
__global__ void __launch_bounds__(256, 2)
ffn_gemm(const float* __restrict__ bias_g) {
    constexpr int KDIM = (MODE == 1) ? D_ : F_;
    constexpr int NDIM = (MODE == 1) ? F_ : D_;
    constexpr int CHUNKS = KDIM / BK;     // 16 / 64

    const int e     = blockIdx.y >> 5;
    const int mtile = blockIdx.y & 31;
    const int cnt   = g_expert_count[e];
    const int m0    = mtile * BM;
    if (m0 >= cnt) return;
    const int nb = blockIdx.x * BN;

    extern __shared__ char smem[];
    const uint32_t sbase = smem_u32(smem);
    int*   sP = (int*)smem;
    float* sW = (float*)(smem + 512);
    float* sB = (float*)(smem + 1024);

    const int tid = threadIdx.x;
    const int warp = tid >> 5, lane = tid & 31;

    {
        if (tid < 128) {
            int idx = m0 + tid;
            int p = (idx < cnt) ? g_expert_list[e * T_ + idx] : -1;
            sP[tid] = p;
            sW[tid] = (MODE == 2 && p >= 0) ? g_topk_w[p] : 0.f;
        } else {
            sB[tid - 128] = __ldg(bias_g + (size_t)e * NDIM + nb + (tid - 128));
        }
    }
    __syncthreads();

    // A gmem sources (running pointers, advanced by BK halves per issued chunk)
    const int qa = tid & 7;
    const __half* aPtr[4];
#pragma unroll
    for (int i = 0; i < 4; i++) {
        int r = (tid >> 3) + i * 32;
        int p = sP[r];
        if (p < 0) p = g_expert_list[e * T_];
        aPtr[i] = ((MODE == 1) ? (g_xh + (size_t)(p >> 1) * D_)
                               : (g_hh + (size_t)p * F_)) + qa * 8;
    }
    const int qb = tid & 15;
    const __half* bPtr = ((MODE == 1) ? g_w1h : g_w2h) + (size_t)e * KDIM * NDIM
                         + (size_t)(tid >> 4) * NDIM + nb + qb * 8;

    // precomputed per-thread smem write offsets (stage-relative)
    uint32_t aDst[4], bDst[4];
#pragma unroll
    for (int i = 0; i < 4; i++) {
        aDst[i] = (uint32_t)(((tid >> 3) + i * 32) * PA_B + qa * 16);
        bDst[i] = (uint32_t)(A_STG + ((tid >> 4) + i * 16) * PB_B + qb * 16);
    }

    uint32_t stgBase[NSTAGE];
#pragma unroll
    for (int s = 0; s < NSTAGE; s++) stgBase[s] = sbase + 1536u + s * STG;

    auto load_stage = [&](int s) {
        const uint32_t base = stgBase[s];
#pragma unroll
        for (int i = 0; i < 4; i++)
            CP16(base + aDst[i], aPtr[i]);
#pragma unroll
        for (int i = 0; i < 4; i++)
            CP16(base + bDst[i], bPtr + (size_t)(i * 16) * NDIM);
        CP_COMMIT();
        // advance running pointers
#pragma unroll
        for (int i = 0; i < 4; i++) aPtr[i] += BK;
        bPtr += BK * (size_t)NDIM;
    };

    const int wm = warp >> 2;
    const int wn = warp & 3;
    const int gid = lane >> 2, tig = lane & 3;

    const uint32_t offA0 = (uint32_t)((wm * 64 + (lane & 15)) * PA_B + (lane >> 4) * 16);
    const uint32_t offB0 = (uint32_t)(A_STG + (((lane >> 3) & 1) * 8 + (lane & 7)) * PB_B
                                      + (wn * 32 + (lane >> 4) * 8) * 2);

    float acc[4][4][4];
#pragma unroll
    for (int mi = 0; mi < 4; mi++)
#pragma unroll
        for (int ni = 0; ni < 4; ni++)
#pragma unroll
            for (int qq = 0; qq < 4; qq++) acc[mi][ni][qq] = 0.f;

    load_stage(0);

    int s = 0;
    for (int c = 0; c < CHUNKS; c++) {
        // pd=1: buffer (c+1)%3 was last read at compute(c-2), fenced by the
        // barrier of iteration c-1 (which precedes this load for all warps).
        if (c + 1 < CHUNKS) {
            int s1 = s + 1; if (s1 >= NSTAGE) s1 = 0;
            load_stage(s1);
            CP_WAIT(1);
        } else {
            CP_WAIT(0);
        }
        __syncthreads();   // single barrier: chunk-c data visible to all warps

        const uint32_t base = stgBase[s];
#pragma unroll
        for (int ks = 0; ks < 4; ks++) {
            uint32_t a[4][4];
            uint32_t b[2][4];
#pragma unroll
            for (int mi = 0; mi < 4; mi++)
                LDSM_X4(a[mi], base + offA0 + (uint32_t)(mi * 16 * PA_B + ks * 32));
#pragma unroll
            for (int np = 0; np < 2; np++)
                LDSM_X4T(b[np], base + offB0 + (uint32_t)(ks * 16 * PB_B + np * 32));
#pragma unroll
            for (int mi = 0; mi < 4; mi++)
#pragma unroll
                for (int ni = 0; ni < 4; ni++)
                    mma_f16(acc[mi][ni], a[mi],
                            b[ni >> 1][(ni & 1) * 2], b[ni >> 1][(ni & 1) * 2 + 1]);
        }
        s++; if (s >= NSTAGE) s = 0;
    }

    // epilogue
#pragma unroll
    for (int mi = 0; mi < 4; mi++) {
#pragma unroll
        for (int ni = 0; ni < 4; ni++) {
            int cl = wn * 32 + ni * 8 + tig * 2;
            int c0 = nb + cl;
            float bi0 = sB[cl];
            float bi1 = sB[cl + 1];
#pragma unroll
            for (int half = 0; half < 2; half++) {
                int r = wm * 64 + mi * 16 + gid + half * 8;
                int p = sP[r];
                if (p >= 0) {
                    float v0 = acc[mi][ni][half * 2 + 0] + bi0;
                    float v1 = acc[mi][ni][half * 2 + 1] + bi1;
                    if (MODE == 1) {
                        v0 = gelu_exact(v0);
                        v1 = gelu_exact(v1);
                        *(__half2*)(g_hh + (size_t)p * F_ + c0) = __floats2half2_rn(v0, v1);
                    } else {
                        float w = sW[r];
                        *(float2*)(g_ybuf + (size_t)p * D_ + c0) = make_float2(v0 * w, v1 * w);
                    }
                }
            }
        }
    }
}

// ---------------- combine (+ counter reset for next replay) ----------------
__global__ void combine_kernel(float* __restrict__ out) {
    int i = blockIdx.x * blockDim.x + threadIdx.x;
    if (i < E_) g_expert_count[i] = 0;   // GEMMs are done; reset for next graph replay
    if (i >= T_ * D_ / 4) return;
    int t = i / (D_ / 4);
    int dq = i % (D_ / 4);
    float4 a = *(const float4*)(g_ybuf + (size_t)(2 * t) * D_ + dq * 4);
    float4 b = *(const float4*)(g_ybuf + (size_t)(2 * t + 1) * D_ + dq * 4);
    float4 r;
    r.x = a.x + b.x; r.y = a.y + b.y; r.z = a.z + b.z; r.w = a.w + b.w;
    *(float4*)(out + (size_t)i * 4) = r;
}

// ---------------- launch ----------------
// Launches: 1 prep (gate+route+xcvt+wcvt), 2 loss1, 3 GEMM1, 4 GEMM2 (ncu slot), 5 combine, 6 loss2
extern "C" void kernel_launch(void* const* d_in, const int* in_sizes, int n_in,
                              void* d_out, int out_size) {
    const float* x  = (const float*)d_in[0];
    const float* Wg = (const float*)d_in[1];
    const float* bg = (const float*)d_in[2];
    const float* W1 = (const float*)d_in[3];
    const float* b1 = (const float*)d_in[4];
    const float* W2 = (const float*)d_in[5];
    const float* b2 = (const float*)d_in[6];
    float* out = (float*)d_out;

    static bool attr_set = false;
    if (!attr_set) {
        cudaFuncSetAttribute(ffn_gemm<1>, cudaFuncAttributeMaxDynamicSharedMemorySize, SMEM_GEMM);
        cudaFuncSetAttribute(ffn_gemm<2>, cudaFuncAttributeMaxDynamicSharedMemorySize, SMEM_GEMM);
        attr_set = true;
    }

    // 1: prep — gate blocks first, then weight-convert blocks (full overlap)
    prep_kernel<<<GATE_BLOCKS + CVT_BLOCKS, 256>>>(x, Wg, bg, W1, W2);
    // 2: loss partials
    loss1_kernel<<<16, 256>>>();
    // 3: GEMM1
    dim3 g1(F_ / BN, E_ * 32);
    ffn_gemm<1><<<g1, 256, SMEM_GEMM>>>(b1);
    // 4: GEMM2  <-- ncu capture slot (first profile of GEMM2)
    dim3 g2(D_ / BN, E_ * 32);
    ffn_gemm<2><<<g2, 256, SMEM_GEMM>>>(b2);
    // 5: combine + counter reset
    combine_kernel<<<(T_ * D_ / 4 + 255) / 256, 256>>>(out);
    // 6: loss final
    loss2_kernel<<<1, 32>>>(out);
}

// round 16
// speedup vs baseline: 1.1839x; 1.0213x over previous
#include <cuda_runtime.h>
#include <cuda_fp16.h>
#include <cstdint>
#include <math.h>

// Problem constants
#define B_    2
#define L_    2048
#define T_    (B_*L_)        // 4096 tokens
#define E_    8
#define D_    1024
#define F_    4096
#define KTOP  2
#define NPAIR (T_*KTOP)      // 8192 pairs

// GEMM tile config: BK=64 chunks, 3 stages, pd=1, one barrier per chunk
#define BM 128
#define BN 128
#define BK 64
#define NSTAGE 3

// smem pitches (bytes)
#define PA_B 144                      // A row: 64 halves = 128B + 16B pad (p16=9, conflict-free)
#define PB_B 272                      // B row: 128 halves = 256B + 16B pad (p16=17, conflict-free)
#define A_STG (BM * PA_B)             // 18432
#define B_STG (BK * PB_B)             // 17408
#define STG   (A_STG + B_STG)         // 35840
#define SMEM_GEMM (1536 + NSTAGE * STG)  // 109056 (2 CTAs = 218112 <= 228KB)

// ---------------- scratch (device globals; device-code access ONLY) ----------------
__device__ __half g_xh[(size_t)T_ * D_];
__device__ __half g_w1h[(size_t)E_ * D_ * F_];   // row-major [e][k=D][n=F]
__device__ __half g_w2h[(size_t)E_ * F_ * D_];   // row-major [e][k=F][n=D]
__device__ __half g_hh[(size_t)NPAIR * F_];
__device__ float  g_ybuf[(size_t)NPAIR * D_];
__device__ float  g_probs[T_ * E_];
__device__ int    g_topk_e[T_ * KTOP];
__device__ float  g_topk_w[T_ * KTOP];
__device__ int    g_expert_list[E_ * T_];
__device__ int    g_expert_count[E_];            // zero-init at load; re-zeroed by combine tail
__device__ float  g_part_pf[16 * E_];
__device__ float  g_part_pp[16 * E_];

// ---------------- helpers ----------------
__device__ __forceinline__ uint32_t smem_u32(const void* p) {
    uint32_t a;
    asm("{ .reg .u64 t; cvta.to.shared.u64 t, %1; cvt.u32.u64 %0, t; }" : "=r"(a) : "l"(p));
    return a;
}

#define CP16(dst, src)  asm volatile("cp.async.cg.shared.global [%0], [%1], 16;" :: "r"(dst), "l"(src))
#define CP_COMMIT()     asm volatile("cp.async.commit_group;" ::: "memory")
#define CP_WAIT(n)      asm volatile("cp.async.wait_group %0;" :: "n"(n) : "memory")

#define LDSM_X4(r, a) \
    asm volatile("ldmatrix.sync.aligned.m8n8.x4.shared.b16 {%0,%1,%2,%3}, [%4];" \
        : "=r"((r)[0]), "=r"((r)[1]), "=r"((r)[2]), "=r"((r)[3]) : "r"(a))

#define LDSM_X4T(r, a) \
    asm volatile("ldmatrix.sync.aligned.m8n8.x4.trans.shared.b16 {%0,%1,%2,%3}, [%4];" \
        : "=r"((r)[0]), "=r"((r)[1]), "=r"((r)[2]), "=r"((r)[3]) : "r"(a))

__device__ __forceinline__ void mma_f16(float c[4], const uint32_t a[4],
                                        uint32_t b0, uint32_t b1) {
    asm volatile(
        "mma.sync.aligned.m16n8k16.row.col.f32.f16.f16.f32 "
        "{%0,%1,%2,%3}, {%4,%5,%6,%7}, {%8,%9}, {%0,%1,%2,%3};"
        : "+f"(c[0]), "+f"(c[1]), "+f"(c[2]), "+f"(c[3])
        : "r"(a[0]), "r"(a[1]), "r"(a[2]), "r"(a[3]), "r"(b0), "r"(b1));
}

__device__ __forceinline__ float gelu_exact(float v) {
    return 0.5f * v * (1.0f + erff(v * 0.70710678118654752f));
}

// ---------------- prep: gate+route+x->fp16 (blocks 0..511) + W1 cvt (rest) ----------------
#define GATE_BLOCKS (T_ / 8)            // 512 blocks x 8 warps = 4096 tokens
#define NW4  (E_ * D_ * F_ / 4)         // float4 units per weight tensor (8388608)
#define CVT_BLOCKS ((NW4 + 255) / 256)  // W1 only

__global__ void prep_kernel(const float* __restrict__ x,
                            const float* __restrict__ Wg,
                            const float* __restrict__ bg,
                            const float* __restrict__ W1) {
    if (blockIdx.x >= GATE_BLOCKS) {
        // ---- W1 conversion path ----
        size_t i = (size_t)(blockIdx.x - GATE_BLOCKS) * blockDim.x + threadIdx.x;
        if (i >= NW4) return;
        float4 v = *(const float4*)(W1 + i * 4);
        ((__half2*)g_w1h)[2 * i]     = __floats2half2_rn(v.x, v.y);
        ((__half2*)g_w1h)[2 * i + 1] = __floats2half2_rn(v.z, v.w);
        return;
    }

    // ---- gate + route + x conversion path ----
    int gwarp = (blockIdx.x * blockDim.x + threadIdx.x) >> 5;
    int lane  = threadIdx.x & 31;
    const float* xr = x + (size_t)gwarp * D_;
    __half* xh = g_xh + (size_t)gwarp * D_;

    float acc[E_];
#pragma unroll
    for (int e = 0; e < E_; e++) acc[e] = 0.f;
    for (int d = lane; d < D_; d += 32) {
        float xv = xr[d];
        xh[d] = __float2half_rn(xv);            // fused x conversion
        float4 w0 = *(const float4*)(Wg + d * E_);
        float4 w1 = *(const float4*)(Wg + d * E_ + 4);
        acc[0] += xv * w0.x; acc[1] += xv * w0.y;
        acc[2] += xv * w0.z; acc[3] += xv * w0.w;
        acc[4] += xv * w1.x; acc[5] += xv * w1.y;
        acc[6] += xv * w1.z; acc[7] += xv * w1.w;
    }
#pragma unroll
    for (int e = 0; e < E_; e++)
#pragma unroll
        for (int off = 16; off > 0; off >>= 1)
            acc[e] += __shfl_xor_sync(0xFFFFFFFFu, acc[e], off);

    if (lane == 0) {
        float s[E_];
#pragma unroll
        for (int e = 0; e < E_; e++) s[e] = acc[e] + bg[e];
        int e0 = 0;
#pragma unroll
        for (int e = 1; e < E_; e++) if (s[e] > s[e0]) e0 = e;
        int e1 = -1;
#pragma unroll
        for (int e = 0; e < E_; e++) {
            if (e == e0) continue;
            if (e1 < 0 || s[e] > s[e1]) e1 = e;
        }
        float z1 = __expf(s[e1] - s[e0]);
        float w0 = 1.0f / (1.0f + z1);
        float w1 = z1 / (1.0f + z1);
        float m = s[e0], zsum = 0.f, p[E_];
#pragma unroll
        for (int e = 0; e < E_; e++) { p[e] = __expf(s[e] - m); zsum += p[e]; }
        float inv = 1.0f / zsum;
#pragma unroll
        for (int e = 0; e < E_; e++) g_probs[gwarp * E_ + e] = p[e] * inv;
        g_topk_e[gwarp * 2 + 0] = e0;
        g_topk_e[gwarp * 2 + 1] = e1;
        g_topk_w[gwarp * 2 + 0] = w0;
        g_topk_w[gwarp * 2 + 1] = w1;
        // fused routing (list order nondeterministic; pair arithmetic order-independent)
        int pos0 = atomicAdd(&g_expert_count[e0], 1);
        g_expert_list[e0 * T_ + pos0] = gwarp * 2 + 0;
        int pos1 = atomicAdd(&g_expert_count[e1], 1);
        g_expert_list[e1 * T_ + pos1] = gwarp * 2 + 1;
    }
}

__global__ void loss1_kernel() {
    __shared__ float spp[E_][257];
    __shared__ float spf[E_][257];
    int tid = threadIdx.x;
    int t = blockIdx.x * 256 + tid;
    float f[E_];
#pragma unroll
    for (int e = 0; e < E_; e++) f[e] = 0.f;
    f[g_topk_e[2 * t]]     += 1.f;
    f[g_topk_e[2 * t + 1]] += 1.f;
#pragma unroll
    for (int e = 0; e < E_; e++) {
        spp[e][tid] = g_probs[t * E_ + e];
        spf[e][tid] = f[e];
    }
    __syncthreads();
    int wid = tid >> 5, lane = tid & 31;
    if (wid < E_) {
        float a = 0.f, b = 0.f;
#pragma unroll
        for (int j = 0; j < 8; j++) {
            a += spf[wid][lane + j * 32];
            b += spp[wid][lane + j * 32];
        }
#pragma unroll
        for (int off = 16; off > 0; off >>= 1) {
            a += __shfl_xor_sync(0xFFFFFFFFu, a, off);
            b += __shfl_xor_sync(0xFFFFFFFFu, b, off);
        }
        if (lane == 0) {
            g_part_pf[blockIdx.x * E_ + wid] = a;
            g_part_pp[blockIdx.x * E_ + wid] = b;
        }
    }
}

__global__ void loss2_kernel(float* __restrict__ out) {
    __shared__ float sl[E_];
    int e = threadIdx.x;
    if (e < E_) {
        float a = 0.f, b = 0.f;
        for (int i = 0; i < 16; i++) { a += g_part_pf[i * E_ + e]; b += g_part_pp[i * E_ + e]; }
        sl[e] = (a / (float)T_) * (b / (float)T_);
    }
    __syncthreads();
    if (e == 0) {
        float loss = 0.f;
        for (int i = 0; i < E_; i++) loss += sl[i];
        out[(size_t)T_ * D_] = loss * (float)E_;
    }
}

// ---------------- BK=64, 3-stage, pd=1, one barrier per chunk ----------------
// MODE 1 additionally converts a grid-stride slice of W2 (fp32->fp16) before
// its GEMM work, hiding the W2 conversion traffic under GEMM1 compute.
// smem: [0,512) sP, [512,1024) sW, [1024,1536) sB, stages at 1536 + s*STG
template <int MODE>
__global__ void __launch_bounds__(256, 2)
ffn_gemm(const float* __restrict__ bias_g, const float* __restrict__ W2src) {
    constexpr int KDIM = (MODE == 1) ? D_ : F_;
    constexpr int NDIM = (MODE == 1) ? F_ : D_;
    constexpr int CHUNKS = KDIM / BK;     // 16 / 64

    const int tid = threadIdx.x;

    if (MODE == 1) {
        // W2 conversion slice: 8192 CTAs x 256 thr -> 4 float4 per thread.
        const uint32_t cta = blockIdx.y * gridDim.x + blockIdx.x;
        size_t i = (size_t)cta * 256 + tid;
        const size_t stride = (size_t)gridDim.x * gridDim.y * 256;
        for (; i < (size_t)NW4; i += stride) {
            float4 v = *(const float4*)(W2src + i * 4);
            ((__half2*)g_w2h)[2 * i]     = __floats2half2_rn(v.x, v.y);
            ((__half2*)g_w2h)[2 * i + 1] = __floats2half2_rn(v.z, v.w);
        }
    }

    const int e     = blockIdx.y >> 5;
    const int mtile = blockIdx.y & 31;
    const int cnt   = g_expert_count[e];
    const int m0    = mtile * BM;
    if (m0 >= cnt) return;
    const int nb = blockIdx.x * BN;

    extern __shared__ char smem[];
    const uint32_t sbase = smem_u32(smem);
    int*   sP = (int*)smem;
    float* sW = (float*)(smem + 512);
    float* sB = (float*)(smem + 1024);

    const int warp = tid >> 5, lane = tid & 31;

    {
        if (tid < 128) {
            int idx = m0 + tid;
            int p = (idx < cnt) ? g_expert_list[e * T_ + idx] : -1;
            sP[tid] = p;
            sW[tid] = (MODE == 2 && p >= 0) ? g_topk_w[p] : 0.f;
        } else {
            sB[tid - 128] = __ldg(bias_g + (size_t)e * NDIM + nb + (tid - 128));
        }
    }
    __syncthreads();

    // A gmem sources (running pointers, advanced by BK halves per issued chunk)
    const int qa = tid & 7;
    const __half* aPtr[4];
#pragma unroll
    for (int i = 0; i < 4; i++) {
        int r = (tid >> 3) + i * 32;
        int p = sP[r];
        if (p < 0) p = g_expert_list[e * T_];
        aPtr[i] = ((MODE == 1) ? (g_xh + (size_t)(p >> 1) * D_)
                               : (g_hh + (size_t)p * F_)) + qa * 8;
    }
    const int qb = tid & 15;
    const __half* bPtr = ((MODE == 1) ? g_w1h : g_w2h) + (size_t)e * KDIM * NDIM
                         + (size_t)(tid >> 4) * NDIM + nb + qb * 8;

    // precomputed per-thread smem write offsets (stage-relative)
    uint32_t aDst[4], bDst[4];
#pragma unroll
    for (int i = 0; i < 4; i++) {
        aDst[i] = (uint32_t)(((tid >> 3) + i * 32) * PA_B + qa * 16);
        bDst[i] = (uint32_t)(A_STG + ((tid >> 4) + i * 16) * PB_B + qb * 16);
    }

    uint32_t stgBase[NSTAGE];
#pragma unroll
    for (int s = 0; s < NSTAGE; s++) stgBase[s] = sbase + 1536u + s * STG;

    auto load_stage = [&](int s) {
        const uint32_t base = stgBase[s];
#pragma unroll
        for (int i = 0; i < 4; i++)
            CP16(base + aDst[i], aPtr[i]);
#pragma unroll
        for (int i = 0; i < 4; i++)
            CP16(base + bDst[i], bPtr + (size_t)(i * 16) * NDIM);
        CP_COMMIT();
        // advance running pointers
#pragma unroll
        for (int i = 0; i < 4; i++) aPtr[i] += BK;
        bPtr += BK * (size_t)NDIM;
    };

    const int wm = warp >> 2;
    const int wn = warp & 3;
    const int gid = lane >> 2, tig = lane & 3;

    const uint32_t offA0 = (uint32_t)((wm * 64 + (lane & 15)) * PA_B + (lane >> 4) * 16);
    const uint32_t offB0 = (uint32_t)(A_STG + (((lane >> 3) & 1) * 8 + (lane & 7)) * PB_B
                                      + (wn * 32 + (lane >> 4) * 8) * 2);

    float acc[4][4][4];
#pragma unroll
    for (int mi = 0; mi < 4; mi++)
#pragma unroll
        for (int ni = 0; ni < 4; ni++)
#pragma unroll
            for (int qq = 0; qq < 4; qq++) acc[mi][ni][qq] = 0.f;

    load_stage(0);

    int s = 0;
    for (int c = 0; c < CHUNKS; c++) {
        // pd=1: buffer (c+1)%3 was last read at compute(c-2), fenced by the
        // barrier of iteration c-1 (which precedes this load for all warps).
        if (c + 1 < CHUNKS) {
            int s1 = s + 1; if (s1 >= NSTAGE) s1 = 0;
            load_stage(s1);
            CP_WAIT(1);
        } else {
            CP_WAIT(0);
        }
        __syncthreads();   // single barrier: chunk-c data visible to all warps

        const uint32_t base = stgBase[s];
#pragma unroll
        for (int ks = 0; ks < 4; ks++) {
            uint32_t a[4][4];
            uint32_t b[2][4];
#pragma unroll
            for (int mi = 0; mi < 4; mi++)
                LDSM_X4(a[mi], base + offA0 + (uint32_t)(mi * 16 * PA_B + ks * 32));
#pragma unroll
            for (int np = 0; np < 2; np++)
                LDSM_X4T(b[np], base + offB0 + (uint32_t)(ks * 16 * PB_B + np * 32));
#pragma unroll
            for (int mi = 0; mi < 4; mi++)
#pragma unroll
                for (int ni = 0; ni < 4; ni++)
                    mma_f16(acc[mi][ni], a[mi],
                            b[ni >> 1][(ni & 1) * 2], b[ni >> 1][(ni & 1) * 2 + 1]);
        }
        s++; if (s >= NSTAGE) s = 0;
    }

    // epilogue
#pragma unroll
    for (int mi = 0; mi < 4; mi++) {
#pragma unroll
        for (int ni = 0; ni < 4; ni++) {
            int cl = wn * 32 + ni * 8 + tig * 2;
            int c0 = nb + cl;
            float bi0 = sB[cl];
            float bi1 = sB[cl + 1];
#pragma unroll
            for (int half = 0; half < 2; half++) {
                int r = wm * 64 + mi * 16 + gid + half * 8;
                int p = sP[r];
                if (p >= 0) {
                    float v0 = acc[mi][ni][half * 2 + 0] + bi0;
                    float v1 = acc[mi][ni][half * 2 + 1] + bi1;
                    if (MODE == 1) {
                        v0 = gelu_exact(v0);
                        v1 = gelu_exact(v1);
                        *(__half2*)(g_hh + (size_t)p * F_ + c0) = __floats2half2_rn(v0, v1);
                    } else {
                        float w = sW[r];
                        *(float2*)(g_ybuf + (size_t)p * D_ + c0) = make_float2(v0 * w, v1 * w);
                    }
                }
            }
        }
    }
}

// ---------------- combine (+ counter reset for next replay) ----------------
__global__ void combine_kernel(float* __restrict__ out) {
    int i = blockIdx.x * blockDim.x + threadIdx.x;
    if (i < E_) g_expert_count[i] = 0;   // GEMMs are done; reset for next graph replay
    if (i >= T_ * D_ / 4) return;
    int t = i / (D_ / 4);
    int dq = i % (D_ / 4);
    float4 a = *(const float4*)(g_ybuf + (size_t)(2 * t) * D_ + dq * 4);
    float4 b = *(const float4*)(g_ybuf + (size_t)(2 * t + 1) * D_ + dq * 4);
    float4 r;
    r.x = a.x + b.x; r.y = a.y + b.y; r.z = a.z + b.z; r.w = a.w + b.w;
    *(float4*)(out + (size_t)i * 4) = r;
}

// ---------------- launch ----------------
// Launches: 1 prep (gate+route+xcvt+W1cvt), 2 loss1, 3 GEMM1 (+W2cvt), 4 GEMM2 (ncu slot),
//           5 combine, 6 loss2
extern "C" void kernel_launch(void* const* d_in, const int* in_sizes, int n_in,
                              void* d_out, int out_size) {
    const float* x  = (const float*)d_in[0];
    const float* Wg = (const float*)d_in[1];
    const float* bg = (const float*)d_in[2];
    const float* W1 = (const float*)d_in[3];
    const float* b1 = (const float*)d_in[4];
    const float* W2 = (const float*)d_in[5];
    const float* b2 = (const float*)d_in[6];
    float* out = (float*)d_out;

    static bool attr_set = false;
    if (!attr_set) {
        cudaFuncSetAttribute(ffn_gemm<1>, cudaFuncAttributeMaxDynamicSharedMemorySize, SMEM_GEMM);
        cudaFuncSetAttribute(ffn_gemm<2>, cudaFuncAttributeMaxDynamicSharedMemorySize, SMEM_GEMM);
        attr_set = true;
    }

    // 1: prep — gate blocks + W1 convert blocks
    prep_kernel<<<GATE_BLOCKS + CVT_BLOCKS, 256>>>(x, Wg, bg, W1);
    // 2: loss partials
    loss1_kernel<<<16, 256>>>();
    // 3: GEMM1 (embedded W2 conversion overlaps with compute)
    dim3 g1(F_ / BN, E_ * 32);
    ffn_gemm<1><<<g1, 256, SMEM_GEMM>>>(b1, W2);
    // 4: GEMM2  <-- ncu capture slot
    dim3 g2(D_ / BN, E_ * 32);
    ffn_gemm<2><<<g2, 256, SMEM_GEMM>>>(b2, (const float*)nullptr);
    // 5: combine + counter reset
    combine_kernel<<<(T_ * D_ / 4 + 255) / 256, 256>>>(out);
    // 6: loss final
    loss2_kernel<<<1, 32>>>(out);
}